// round 2
// baseline (speedup 1.0000x reference)
#include <cuda_runtime.h>
#include <math.h>

#define NB 8
#define LQ 2048
#define DD 512
#define DECAYF 0.2f
#define DP 516   // padded row stride (floats) for attention smem tiles

// Scratch (device globals: allocation-free per harness rules)
__device__ float g_Xs[NB * LQ * DD];          // routed seasonal vectors
__device__ float g_Xt[NB * LQ * DD];          // routed trend vectors
__device__ float g_cat[NB * LQ * 2 * DD];     // [seasonal_f | trend_f] concat

// ---------------------------------------------------------------------------
// Block-wide sum reduction (256 threads)
// ---------------------------------------------------------------------------
__device__ __forceinline__ float blockReduceSum(float v, float* red) {
    #pragma unroll
    for (int o = 16; o > 0; o >>= 1) v += __shfl_xor_sync(0xffffffffu, v, o);
    int tid = threadIdx.x;
    if ((tid & 31) == 0) red[tid >> 5] = v;
    __syncthreads();
    if (tid < 32) {
        float x = (tid < 8) ? red[tid] : 0.f;
        #pragma unroll
        for (int o = 4; o > 0; o >>= 1) x += __shfl_xor_sync(0xffffffffu, x, o);
        if (tid == 0) red[0] = x;
    }
    __syncthreads();
    float r = red[0];
    __syncthreads();
    return r;
}

// Dynamic routing, M=2 capsules, 3 iterations. Each thread owns 2 channels.
__device__ __forceinline__ void routing2(const float u0[2], const float u1[2],
                                         float vout[2], float* red) {
    float b0 = 0.f, b1 = 0.f;
    #pragma unroll
    for (int it = 0; it < 3; it++) {
        float mx = fmaxf(b0, b1);
        float e0 = __expf(b0 - mx), e1 = __expf(b1 - mx);
        float inv = 1.f / (e0 + e1);
        float c0 = e0 * inv, c1 = e1 * inv;
        float s0 = c0 * u0[0] + c1 * u1[0];
        float s1 = c0 * u0[1] + c1 * u1[1];
        float n2 = blockReduceSum(s0 * s0 + s1 * s1, red);
        float nrm = sqrtf(n2);
        float scl = n2 / ((1.f + n2) * (nrm + 1e-9f));  // squash
        vout[0] = scl * s0;
        vout[1] = scl * s1;
        if (it < 2) {
            b0 += blockReduceSum(u0[0] * vout[0] + u0[1] * vout[1], red);
            b1 += blockReduceSum(u1[0] * vout[0] + u1[1] * vout[1], red);
        }
    }
}

// ---------------------------------------------------------------------------
// Kernel 1: causal depthwise convs + capsule routing -> g_Xs, g_Xt
// grid = N*L blocks, 256 threads (each thread handles channels tid and tid+256)
// ---------------------------------------------------------------------------
__global__ void prep_kernel(const float* __restrict__ x,
                            const float* __restrict__ w3,
                            const float* __restrict__ w5) {
    __shared__ float red[8];
    int row = blockIdx.x;
    int n = row >> 11;          // row / 2048
    int l = row & 2047;
    int tid = threadIdx.x;

    float xv[2], t3v[2], t5v[2];
    #pragma unroll
    for (int i = 0; i < 2; i++) {
        int c = tid + i * 256;
        const float* xb = x + (size_t)n * LQ * DD + c;
        float a3 = 0.f, a5 = 0.f, xx = 0.f;
        #pragma unroll
        for (int j = 0; j < 5; j++) {
            int ll = l - 4 + j;
            xx = (ll >= 0) ? xb[(size_t)ll * DD] : 0.f;
            a5 += w5[c * 5 + j] * xx;
            if (j >= 2) a3 += w3[c * 3 + (j - 2)] * xx;
        }
        xv[i] = xx;     // x[l][c]
        t3v[i] = a3;
        t5v[i] = a5;
    }

    float u0[2], u1[2], v[2];
    // seasonal capsules: [x - trend3, x - trend5]
    u0[0] = xv[0] - t3v[0]; u0[1] = xv[1] - t3v[1];
    u1[0] = xv[0] - t5v[0]; u1[1] = xv[1] - t5v[1];
    routing2(u0, u1, v, red);
    g_Xs[(size_t)row * DD + tid]       = v[0];
    g_Xs[(size_t)row * DD + tid + 256] = v[1];

    // trend capsules: [trend3, trend5]
    u0[0] = t3v[0]; u0[1] = t3v[1];
    u1[0] = t5v[0]; u1[1] = t5v[1];
    routing2(u0, u1, v, red);
    g_Xt[(size_t)row * DD + tid]       = v[0];
    g_Xt[(size_t)row * DD + tid + 256] = v[1];
}

// ---------------------------------------------------------------------------
// Kernel 2: causal self-attention with -decay*(i-j) bias (flash-style)
// grid = (L/32, N, 2), 256 threads, dynamic smem = (64*DP + 32*33)*4 bytes
// Writes directly into g_cat at column offset z*512.
// ---------------------------------------------------------------------------
__global__ void __launch_bounds__(256, 1) attn_kernel() {
    extern __shared__ float sm[];
    float* Qs = sm;                 // 32 x DP
    float* Ks = sm + 32 * DP;       // 32 x DP (keys == values)
    float* Ss = sm + 64 * DP;       // 32 x 33 score tile

    int zb = blockIdx.z;
    const float* X = zb ? g_Xt : g_Xs;
    int n = blockIdx.y;
    int qb = blockIdx.x;
    int tid = threadIdx.x;
    const float* Xn = X + (size_t)n * LQ * DD;
    int q0 = qb * 32;

    // load Q tile (32 rows x 512 floats, float4)
    for (int i = tid; i < 32 * 128; i += 256) {
        int r = i >> 7, c4 = i & 127;
        float4 val = ((const float4*)(Xn + (size_t)(q0 + r) * DD))[c4];
        *(float4*)&Qs[r * DP + c4 * 4] = val;
    }

    int rr = tid & 31;      // output row within tile
    int g  = tid >> 5;      // column slice: owns cols [g*64, g*64+64)
    float acc[64];
    #pragma unroll
    for (int j = 0; j < 64; j++) acc[j] = 0.f;
    float mrow = -3.0e30f, lrow = 0.f;

    int str = tid >> 4;     // score rows {str, str+16}
    int stc = tid & 15;     // score cols {stc, stc+16}

    for (int kb = 0; kb <= qb; kb++) {
        __syncthreads();    // prev PV reads of Ks/Ss done
        for (int i = tid; i < 32 * 128; i += 256) {
            int r = i >> 7, c4 = i & 127;
            float4 val = ((const float4*)(Xn + (size_t)(kb * 32 + r) * DD))[c4];
            *(float4*)&Ks[r * DP + c4 * 4] = val;
        }
        __syncthreads();

        // --- scores: 2x2 per thread, dot over D=512 ---
        float s00 = 0.f, s01 = 0.f, s10 = 0.f, s11 = 0.f;
        const float4* Qa  = (const float4*)(Qs + str * DP);
        const float4* Qb2 = (const float4*)(Qs + (str + 16) * DP);
        const float4* Ka  = (const float4*)(Ks + stc * DP);
        const float4* Kb2 = (const float4*)(Ks + (stc + 16) * DP);
        #pragma unroll 4
        for (int d4 = 0; d4 < 128; d4++) {
            float4 qa = Qa[d4], qb2 = Qb2[d4], ka = Ka[d4], kb2 = Kb2[d4];
            s00 = fmaf(qa.x, ka.x, s00);  s00 = fmaf(qa.y, ka.y, s00);
            s00 = fmaf(qa.z, ka.z, s00);  s00 = fmaf(qa.w, ka.w, s00);
            s01 = fmaf(qa.x, kb2.x, s01); s01 = fmaf(qa.y, kb2.y, s01);
            s01 = fmaf(qa.z, kb2.z, s01); s01 = fmaf(qa.w, kb2.w, s01);
            s10 = fmaf(qb2.x, ka.x, s10); s10 = fmaf(qb2.y, ka.y, s10);
            s10 = fmaf(qb2.z, ka.z, s10); s10 = fmaf(qb2.w, ka.w, s10);
            s11 = fmaf(qb2.x, kb2.x, s11); s11 = fmaf(qb2.y, kb2.y, s11);
            s11 = fmaf(qb2.z, kb2.z, s11); s11 = fmaf(qb2.w, kb2.w, s11);
        }
        // write scores with causal mask + decay bias
        {
            int kcol = kb * 32;
            int qr, kc;
            qr = q0 + str;      kc = kcol + stc;
            Ss[str * 33 + stc]             = (qr >= kc) ? s00 - DECAYF * (float)(qr - kc) : -3.0e30f;
            qr = q0 + str;      kc = kcol + stc + 16;
            Ss[str * 33 + stc + 16]        = (qr >= kc) ? s01 - DECAYF * (float)(qr - kc) : -3.0e30f;
            qr = q0 + str + 16; kc = kcol + stc;
            Ss[(str + 16) * 33 + stc]      = (qr >= kc) ? s10 - DECAYF * (float)(qr - kc) : -3.0e30f;
            qr = q0 + str + 16; kc = kcol + stc + 16;
            Ss[(str + 16) * 33 + stc + 16] = (qr >= kc) ? s11 - DECAYF * (float)(qr - kc) : -3.0e30f;
        }
        __syncthreads();

        // --- online softmax + PV (each thread: row rr, 64 cols) ---
        float tmax = -3.0e30f;
        #pragma unroll
        for (int k = 0; k < 32; k++) tmax = fmaxf(tmax, Ss[rr * 33 + k]);
        float newm = fmaxf(mrow, tmax);
        float corr = __expf(mrow - newm);
        lrow *= corr;
        #pragma unroll
        for (int j = 0; j < 64; j++) acc[j] *= corr;

        #pragma unroll 4
        for (int k = 0; k < 32; k++) {
            float p = __expf(Ss[rr * 33 + k] - newm);
            lrow += p;
            const float4* Vk = (const float4*)(Ks + k * DP + g * 64);
            #pragma unroll
            for (int j4 = 0; j4 < 16; j4++) {
                float4 vv = Vk[j4];
                acc[j4 * 4 + 0] = fmaf(p, vv.x, acc[j4 * 4 + 0]);
                acc[j4 * 4 + 1] = fmaf(p, vv.y, acc[j4 * 4 + 1]);
                acc[j4 * 4 + 2] = fmaf(p, vv.z, acc[j4 * 4 + 2]);
                acc[j4 * 4 + 3] = fmaf(p, vv.w, acc[j4 * 4 + 3]);
            }
        }
        mrow = newm;
    }

    float inv = 1.f / lrow;
    float* outp = g_cat + (size_t)(n * LQ + q0 + rr) * (2 * DD) + zb * DD + g * 64;
    #pragma unroll
    for (int j4 = 0; j4 < 16; j4++) {
        float4 vv = make_float4(acc[j4 * 4 + 0] * inv, acc[j4 * 4 + 1] * inv,
                                acc[j4 * 4 + 2] * inv, acc[j4 * 4 + 3] * inv);
        ((float4*)outp)[j4] = vv;
    }
}

// ---------------------------------------------------------------------------
// Kernel 3: out[16384,512] = g_cat[16384,1024] @ W[512,1024]^T + bias
// 64x64x32 tiles, 256 threads, 4x4 microtile per thread
// ---------------------------------------------------------------------------
__global__ void fusion_kernel(const float* __restrict__ W,
                              const float* __restrict__ bias,
                              float* __restrict__ out) {
    __shared__ float As[32][68];
    __shared__ float Bs[32][68];
    int bm = blockIdx.x * 64;
    int bn = blockIdx.y * 64;
    int tid = threadIdx.x;
    int ty = tid >> 4, tx = tid & 15;
    float acc[4][4] = {{0.f}};

    for (int k0 = 0; k0 < 1024; k0 += 32) {
        __syncthreads();
        #pragma unroll
        for (int i = 0; i < 2; i++) {
            int idx = tid + i * 256;
            int row = idx >> 3, kq = idx & 7;
            float4 a = *(const float4*)(g_cat + (size_t)(bm + row) * 1024 + k0 + kq * 4);
            As[kq * 4 + 0][row] = a.x; As[kq * 4 + 1][row] = a.y;
            As[kq * 4 + 2][row] = a.z; As[kq * 4 + 3][row] = a.w;
            float4 b = *(const float4*)(W + (size_t)(bn + row) * 1024 + k0 + kq * 4);
            Bs[kq * 4 + 0][row] = b.x; Bs[kq * 4 + 1][row] = b.y;
            Bs[kq * 4 + 2][row] = b.z; Bs[kq * 4 + 3][row] = b.w;
        }
        __syncthreads();
        #pragma unroll
        for (int kk = 0; kk < 32; kk++) {
            float4 av = *(const float4*)&As[kk][ty * 4];
            float4 bv = *(const float4*)&Bs[kk][tx * 4];
            float a_[4] = {av.x, av.y, av.z, av.w};
            float b_[4] = {bv.x, bv.y, bv.z, bv.w};
            #pragma unroll
            for (int i2 = 0; i2 < 4; i2++)
                #pragma unroll
                for (int j2 = 0; j2 < 4; j2++)
                    acc[i2][j2] = fmaf(a_[i2], b_[j2], acc[i2][j2]);
        }
    }

    #pragma unroll
    for (int i2 = 0; i2 < 4; i2++) {
        int orow = bm + ty * 4 + i2;
        float4 r;
        r.x = acc[i2][0] + bias[bn + tx * 4 + 0];
        r.y = acc[i2][1] + bias[bn + tx * 4 + 1];
        r.z = acc[i2][2] + bias[bn + tx * 4 + 2];
        r.w = acc[i2][3] + bias[bn + tx * 4 + 3];
        *(float4*)(out + (size_t)orow * 512 + bn + tx * 4) = r;
    }
}

// ---------------------------------------------------------------------------
extern "C" void kernel_launch(void* const* d_in, const int* in_sizes, int n_in,
                              void* d_out, int out_size) {
    const float* x  = (const float*)d_in[0];  // qa_embed_data [8,2048,512]
    const float* w3 = (const float*)d_in[1];  // conv_w3 [512,1,3]
    const float* w5 = (const float*)d_in[2];  // conv_w5 [512,1,5]
    const float* fw = (const float*)d_in[3];  // fusion_w [512,1024]
    const float* fb = (const float*)d_in[4];  // fusion_b [512]
    float* out = (float*)d_out;               // [8,2048,512]

    prep_kernel<<<NB * LQ, 256>>>(x, w3, w5);

    size_t smem = (size_t)(64 * DP + 32 * 33) * sizeof(float);  // 136320 B
    cudaFuncSetAttribute(attn_kernel,
                         cudaFuncAttributeMaxDynamicSharedMemorySize, (int)smem);
    dim3 ga(LQ / 32, NB, 2);
    attn_kernel<<<ga, 256, smem>>>();

    dim3 gf((NB * LQ) / 64, DD / 64);
    fusion_kernel<<<gf, 256>>>(fw, fb, out);
}

// round 3
// speedup vs baseline: 1.7774x; 1.7774x over previous
#include <cuda_runtime.h>
#include <math.h>

#define NB 8
#define LQ 2048
#define DD 512
#define DECAYF 0.2f
#define QP 516      // Q tile smem row stride (pad ≡ 4 mod 32 -> conflict-free A-frag LDS)
#define KP 516      // K/V tile smem row stride
#define PP 36       // P tile smem row stride

// Scratch (device globals: allocation-free per harness rules)
__device__ float g_Xs[NB * LQ * DD];
__device__ float g_Xt[NB * LQ * DD];
__device__ float g_cat[NB * LQ * 2 * DD];

// ---------------------------------------------------------------------------
// tf32 mma.sync helper: D += A(16x8) * B(8x8), accumulate in place
// ---------------------------------------------------------------------------
__device__ __forceinline__ void mma_tf32(float* c,
                                         unsigned a0, unsigned a1, unsigned a2, unsigned a3,
                                         unsigned b0, unsigned b1) {
    asm volatile(
        "mma.sync.aligned.m16n8k8.row.col.f32.tf32.tf32.f32 "
        "{%0,%1,%2,%3}, {%4,%5,%6,%7}, {%8,%9}, {%0,%1,%2,%3};\n"
        : "+f"(c[0]), "+f"(c[1]), "+f"(c[2]), "+f"(c[3])
        : "r"(a0), "r"(a1), "r"(a2), "r"(a3), "r"(b0), "r"(b1));
}

// Dekker split: x = hi(tf32-truncated) + lo. hi·hi + hi·lo + lo·hi ~ fp32 acc.
__device__ __forceinline__ void split2(float x, unsigned& hi, unsigned& lo) {
    unsigned xb = __float_as_uint(x);
    hi = xb & 0xffffe000u;
    lo = __float_as_uint(x - __uint_as_float(hi));
}

// ---------------------------------------------------------------------------
// Block-wide sum reduction (256 threads) for prep
// ---------------------------------------------------------------------------
__device__ __forceinline__ float blockReduceSum(float v, float* red) {
    #pragma unroll
    for (int o = 16; o > 0; o >>= 1) v += __shfl_xor_sync(0xffffffffu, v, o);
    int tid = threadIdx.x;
    if ((tid & 31) == 0) red[tid >> 5] = v;
    __syncthreads();
    if (tid < 32) {
        float x = (tid < 8) ? red[tid] : 0.f;
        #pragma unroll
        for (int o = 4; o > 0; o >>= 1) x += __shfl_xor_sync(0xffffffffu, x, o);
        if (tid == 0) red[0] = x;
    }
    __syncthreads();
    float r = red[0];
    __syncthreads();
    return r;
}

__device__ __forceinline__ void routing2(const float u0[2], const float u1[2],
                                         float vout[2], float* red) {
    float b0 = 0.f, b1 = 0.f;
    #pragma unroll
    for (int it = 0; it < 3; it++) {
        float mx = fmaxf(b0, b1);
        float e0 = __expf(b0 - mx), e1 = __expf(b1 - mx);
        float inv = 1.f / (e0 + e1);
        float c0 = e0 * inv, c1 = e1 * inv;
        float s0 = c0 * u0[0] + c1 * u1[0];
        float s1 = c0 * u0[1] + c1 * u1[1];
        float n2 = blockReduceSum(s0 * s0 + s1 * s1, red);
        float nrm = sqrtf(n2);
        float scl = n2 / ((1.f + n2) * (nrm + 1e-9f));
        vout[0] = scl * s0;
        vout[1] = scl * s1;
        if (it < 2) {
            b0 += blockReduceSum(u0[0] * vout[0] + u0[1] * vout[1], red);
            b1 += blockReduceSum(u1[0] * vout[0] + u1[1] * vout[1], red);
        }
    }
}

// ---------------------------------------------------------------------------
// Kernel 1: causal depthwise convs + capsule routing
// ---------------------------------------------------------------------------
__global__ void prep_kernel(const float* __restrict__ x,
                            const float* __restrict__ w3,
                            const float* __restrict__ w5) {
    __shared__ float red[8];
    int row = blockIdx.x;
    int n = row >> 11;
    int l = row & 2047;
    int tid = threadIdx.x;

    float xv[2], t3v[2], t5v[2];
    #pragma unroll
    for (int i = 0; i < 2; i++) {
        int c = tid + i * 256;
        const float* xb = x + (size_t)n * LQ * DD + c;
        float a3 = 0.f, a5 = 0.f, xx = 0.f;
        #pragma unroll
        for (int j = 0; j < 5; j++) {
            int ll = l - 4 + j;
            xx = (ll >= 0) ? xb[(size_t)ll * DD] : 0.f;
            a5 += w5[c * 5 + j] * xx;
            if (j >= 2) a3 += w3[c * 3 + (j - 2)] * xx;
        }
        xv[i] = xx; t3v[i] = a3; t5v[i] = a5;
    }

    float u0[2], u1[2], v[2];
    u0[0] = xv[0] - t3v[0]; u0[1] = xv[1] - t3v[1];
    u1[0] = xv[0] - t5v[0]; u1[1] = xv[1] - t5v[1];
    routing2(u0, u1, v, red);
    g_Xs[(size_t)row * DD + tid]       = v[0];
    g_Xs[(size_t)row * DD + tid + 256] = v[1];

    u0[0] = t3v[0]; u0[1] = t3v[1];
    u1[0] = t5v[0]; u1[1] = t5v[1];
    routing2(u0, u1, v, red);
    g_Xt[(size_t)row * DD + tid]       = v[0];
    g_Xt[(size_t)row * DD + tid + 256] = v[1];
}

// ---------------------------------------------------------------------------
// Kernel 2: flash attention, tf32 mma.sync 3-pass, 32x32 tiles
// grid = (L/32, N, 2), 256 threads
// ---------------------------------------------------------------------------
__global__ void __launch_bounds__(256, 1) attn_kernel() {
    extern __shared__ float sm[];
    float* Qs     = sm;                  // 32 x QP
    float* Ks     = Qs + 32 * QP;        // 32 x KP (keys == values)
    float* Ps     = Ks + 32 * KP;        // 32 x PP
    float* redm   = Ps + 32 * PP;        // 4 x 32
    float* redl   = redm + 128;          // 4 x 32
    float* m_s    = redl + 128;          // 32
    float* l_s    = m_s + 32;            // 32
    float* corr_s = l_s + 32;            // 32

    int zb = blockIdx.z;
    const float* X = zb ? g_Xt : g_Xs;
    int n = blockIdx.y;
    int qb = blockIdx.x;
    int tid = threadIdx.x;
    int w = tid >> 5, lane = tid & 31;
    int g4 = lane >> 2, tig = lane & 3;
    const float* Xn = X + (size_t)n * LQ * DD;
    int q0 = qb * 32;

    // load Q tile
    for (int i = tid; i < 32 * 128; i += 256) {
        int r = i >> 7, c4 = i & 127;
        *(float4*)&Qs[r * QP + c4 * 4] = ((const float4*)(Xn + (size_t)(q0 + r) * DD))[c4];
    }
    if (tid < 32) { m_s[tid] = -3.0e30f; l_s[tid] = 0.f; }

    // partitions: scores: warp = (rg rowgroup of 16) x (cg colgroup of 8)
    //             PV:     warp = (rg rowgroup of 16) x (cg2 colgroup of 128)
    int rg = w & 1, cg = w >> 1;

    float acc[16][4];
    #pragma unroll
    for (int i = 0; i < 16; i++) { acc[i][0] = acc[i][1] = acc[i][2] = acc[i][3] = 0.f; }

    int ar0 = (rg * 16 + g4) * QP;
    int ar1 = (rg * 16 + g4 + 8) * QP;
    int br  = (cg * 8 + g4) * KP;
    int par0 = (rg * 16 + g4) * PP;
    int par1 = (rg * 16 + g4 + 8) * PP;

    for (int kb = 0; kb <= qb; kb++) {
        __syncthreads();                        // S1: protect Ks/Ps/redl
        for (int i = tid; i < 32 * 128; i += 256) {
            int r = i >> 7, c4 = i & 127;
            *(float4*)&Ks[r * KP + c4 * 4] = ((const float4*)(Xn + (size_t)(kb * 32 + r) * DD))[c4];
        }
        __syncthreads();                        // S2: Ks ready

        // --- scores: S = Q K^T, 3-pass tf32 ---
        float sc[4] = {0.f, 0.f, 0.f, 0.f};
        #pragma unroll 8
        for (int ks = 0; ks < 64; ks++) {
            int k0 = ks * 8;
            unsigned h0, l0, h1, l1, h2, l2, h3, l3, hb0, lb0, hb1, lb1;
            split2(Qs[ar0 + k0 + tig],     h0, l0);
            split2(Qs[ar1 + k0 + tig],     h1, l1);
            split2(Qs[ar0 + k0 + tig + 4], h2, l2);
            split2(Qs[ar1 + k0 + tig + 4], h3, l3);
            split2(Ks[br + k0 + tig],      hb0, lb0);
            split2(Ks[br + k0 + tig + 4],  hb1, lb1);
            mma_tf32(sc, h0, h1, h2, h3, hb0, hb1);
            mma_tf32(sc, h0, h1, h2, h3, lb0, lb1);
            mma_tf32(sc, l0, l1, l2, l3, hb0, hb1);
        }
        // bias + causal mask
        int r0 = q0 + rg * 16 + g4, r1 = r0 + 8;
        int c0 = kb * 32 + cg * 8 + 2 * tig, c1 = c0 + 1;
        sc[0] = (r0 >= c0) ? sc[0] - DECAYF * (float)(r0 - c0) : -3.0e30f;
        sc[1] = (r0 >= c1) ? sc[1] - DECAYF * (float)(r0 - c1) : -3.0e30f;
        sc[2] = (r1 >= c0) ? sc[2] - DECAYF * (float)(r1 - c0) : -3.0e30f;
        sc[3] = (r1 >= c1) ? sc[3] - DECAYF * (float)(r1 - c1) : -3.0e30f;

        // warp-level row max over this warp's 8 cols
        float m0 = fmaxf(sc[0], sc[1]);
        float m1 = fmaxf(sc[2], sc[3]);
        m0 = fmaxf(m0, __shfl_xor_sync(0xffffffffu, m0, 1));
        m0 = fmaxf(m0, __shfl_xor_sync(0xffffffffu, m0, 2));
        m1 = fmaxf(m1, __shfl_xor_sync(0xffffffffu, m1, 1));
        m1 = fmaxf(m1, __shfl_xor_sync(0xffffffffu, m1, 2));
        if (tig == 0) {
            redm[cg * 32 + rg * 16 + g4]     = m0;
            redm[cg * 32 + rg * 16 + g4 + 8] = m1;
        }
        __syncthreads();                        // S3: redm ready
        if (w == 0) {
            int r = lane;
            float tm = fmaxf(fmaxf(redm[r], redm[32 + r]), fmaxf(redm[64 + r], redm[96 + r]));
            float mo = m_s[r];
            float mn = fmaxf(mo, tm);
            m_s[r] = mn;
            corr_s[r] = __expf(mo - mn);
        }
        __syncthreads();                        // S4: m_s/corr_s ready

        // P = exp(S - m), write to Ps + partial sums
        {
            float mn0 = m_s[rg * 16 + g4];
            float mn1 = m_s[rg * 16 + g4 + 8];
            float p0 = __expf(sc[0] - mn0);
            float p1 = __expf(sc[1] - mn0);
            float p2 = __expf(sc[2] - mn1);
            float p3 = __expf(sc[3] - mn1);
            *(float2*)&Ps[par0 + cg * 8 + 2 * tig] = make_float2(p0, p1);
            *(float2*)&Ps[par1 + cg * 8 + 2 * tig] = make_float2(p2, p3);
            float s0 = p0 + p1, s1 = p2 + p3;
            s0 += __shfl_xor_sync(0xffffffffu, s0, 1);
            s0 += __shfl_xor_sync(0xffffffffu, s0, 2);
            s1 += __shfl_xor_sync(0xffffffffu, s1, 1);
            s1 += __shfl_xor_sync(0xffffffffu, s1, 2);
            if (tig == 0) {
                redl[cg * 32 + rg * 16 + g4]     = s0;
                redl[cg * 32 + rg * 16 + g4 + 8] = s1;
            }
        }
        __syncthreads();                        // S5: Ps + redl ready
        if (w == 0) {
            int r = lane;
            l_s[r] = l_s[r] * corr_s[r] + redl[r] + redl[32 + r] + redl[64 + r] + redl[96 + r];
        }

        // --- PV: O += P V, 3-pass tf32 ---
        float cr0 = corr_s[rg * 16 + g4];
        float cr1 = corr_s[rg * 16 + g4 + 8];
        #pragma unroll
        for (int nf = 0; nf < 16; nf++) {
            acc[nf][0] *= cr0; acc[nf][1] *= cr0;
            acc[nf][2] *= cr1; acc[nf][3] *= cr1;
        }
        #pragma unroll
        for (int ks = 0; ks < 4; ks++) {
            int k0 = ks * 8;
            unsigned h0, l0, h1, l1, h2, l2, h3, l3;
            split2(Ps[par0 + k0 + tig],     h0, l0);
            split2(Ps[par1 + k0 + tig],     h1, l1);
            split2(Ps[par0 + k0 + tig + 4], h2, l2);
            split2(Ps[par1 + k0 + tig + 4], h3, l3);
            int vb0 = (k0 + tig) * KP;
            int vb1 = (k0 + tig + 4) * KP;
            #pragma unroll
            for (int nf = 0; nf < 16; nf++) {
                int n0 = cg * 128 + nf * 8 + g4;
                unsigned hv0, lv0, hv1, lv1;
                split2(Ks[vb0 + n0], hv0, lv0);
                split2(Ks[vb1 + n0], hv1, lv1);
                mma_tf32(acc[nf], h0, h1, h2, h3, hv0, hv1);
                mma_tf32(acc[nf], h0, h1, h2, h3, lv0, lv1);
                mma_tf32(acc[nf], l0, l1, l2, l3, hv0, hv1);
            }
        }
    }
    __syncthreads();

    float li0 = 1.f / l_s[rg * 16 + g4];
    float li1 = 1.f / l_s[rg * 16 + g4 + 8];
    int orow0 = n * LQ + q0 + rg * 16 + g4;
    int orow1 = orow0 + 8;
    #pragma unroll
    for (int nf = 0; nf < 16; nf++) {
        int col = zb * DD + cg * 128 + nf * 8 + 2 * tig;
        *(float2*)&g_cat[(size_t)orow0 * (2 * DD) + col] =
            make_float2(acc[nf][0] * li0, acc[nf][1] * li0);
        *(float2*)&g_cat[(size_t)orow1 * (2 * DD) + col] =
            make_float2(acc[nf][2] * li1, acc[nf][3] * li1);
    }
}

// ---------------------------------------------------------------------------
// Kernel 3: out[16384,512] = g_cat[16384,1024] @ W[512,1024]^T + bias
// tf32 mma.sync 3-pass, 64x64 tiles
// ---------------------------------------------------------------------------
__global__ void __launch_bounds__(256) fusion_kernel(const float* __restrict__ W,
                                                     const float* __restrict__ bias,
                                                     float* __restrict__ out) {
    __shared__ float As[64 * 36];
    __shared__ float Bs[64 * 36];
    int bm = blockIdx.x * 64;
    int bn = blockIdx.y * 64;
    int tid = threadIdx.x;
    int w = tid >> 5, lane = tid & 31;
    int g4 = lane >> 2, tig = lane & 3;
    int rg = w & 3, cg = w >> 2;

    float acc[4][4];
    #pragma unroll
    for (int i = 0; i < 4; i++) { acc[i][0] = acc[i][1] = acc[i][2] = acc[i][3] = 0.f; }

    int ar0 = (rg * 16 + g4) * 36;
    int ar1 = (rg * 16 + g4 + 8) * 36;

    for (int kc = 0; kc < 32; kc++) {
        __syncthreads();
        #pragma unroll
        for (int i = 0; i < 2; i++) {
            int idx = tid + i * 256;
            int r = idx >> 3, c = idx & 7;
            *(float4*)&As[r * 36 + c * 4] =
                *(const float4*)&g_cat[(size_t)(bm + r) * 1024 + kc * 32 + c * 4];
            *(float4*)&Bs[r * 36 + c * 4] =
                *(const float4*)&W[(size_t)(bn + r) * 1024 + kc * 32 + c * 4];
        }
        __syncthreads();
        #pragma unroll
        for (int ks = 0; ks < 4; ks++) {
            int k0 = ks * 8;
            unsigned h0, l0, h1, l1, h2, l2, h3, l3;
            split2(As[ar0 + k0 + tig],     h0, l0);
            split2(As[ar1 + k0 + tig],     h1, l1);
            split2(As[ar0 + k0 + tig + 4], h2, l2);
            split2(As[ar1 + k0 + tig + 4], h3, l3);
            #pragma unroll
            for (int nf = 0; nf < 4; nf++) {
                int brow = (cg * 32 + nf * 8 + g4) * 36;
                unsigned hb0, lb0, hb1, lb1;
                split2(Bs[brow + k0 + tig],     hb0, lb0);
                split2(Bs[brow + k0 + tig + 4], hb1, lb1);
                mma_tf32(acc[nf], h0, h1, h2, h3, hb0, hb1);
                mma_tf32(acc[nf], h0, h1, h2, h3, lb0, lb1);
                mma_tf32(acc[nf], l0, l1, l2, l3, hb0, hb1);
            }
        }
    }

    int orow0 = bm + rg * 16 + g4, orow1 = orow0 + 8;
    #pragma unroll
    for (int nf = 0; nf < 4; nf++) {
        int col = bn + cg * 32 + nf * 8 + 2 * tig;
        float b0v = bias[col], b1v = bias[col + 1];
        *(float2*)&out[(size_t)orow0 * 512 + col] = make_float2(acc[nf][0] + b0v, acc[nf][1] + b1v);
        *(float2*)&out[(size_t)orow1 * 512 + col] = make_float2(acc[nf][2] + b0v, acc[nf][3] + b1v);
    }
}

// ---------------------------------------------------------------------------
extern "C" void kernel_launch(void* const* d_in, const int* in_sizes, int n_in,
                              void* d_out, int out_size) {
    const float* x  = (const float*)d_in[0];
    const float* w3 = (const float*)d_in[1];
    const float* w5 = (const float*)d_in[2];
    const float* fw = (const float*)d_in[3];
    const float* fb = (const float*)d_in[4];
    float* out = (float*)d_out;

    prep_kernel<<<NB * LQ, 256>>>(x, w3, w5);

    size_t smem = (size_t)(32 * QP + 32 * KP + 32 * PP + 128 + 128 + 96) * sizeof(float);
    cudaFuncSetAttribute(attn_kernel,
                         cudaFuncAttributeMaxDynamicSharedMemorySize, (int)smem);
    dim3 ga(LQ / 32, NB, 2);
    attn_kernel<<<ga, 256, smem>>>();

    dim3 gf((NB * LQ) / 64, DD / 64);
    fusion_kernel<<<gf, 256>>>(fw, fb, out);
}

// round 4
// speedup vs baseline: 1.7790x; 1.0009x over previous
#include <cuda_runtime.h>
#include <math.h>

#define NB 8
#define LQ 2048
#define DD 512
#define DECAYF 0.2f
#define QP 516      // Q tile smem row stride (pad ≡ 4 mod 32 -> conflict-free A-frag LDS)
#define KP 516      // K/V tile smem row stride
#define PP 36       // P tile smem row stride

// Scratch (device globals: allocation-free per harness rules)
__device__ float g_Xs[NB * LQ * DD];
__device__ float g_Xt[NB * LQ * DD];
__device__ float g_cat[NB * LQ * 2 * DD];

// ---------------------------------------------------------------------------
// tf32 mma.sync helper: D += A(16x8) * B(8x8), accumulate in place
// ---------------------------------------------------------------------------
__device__ __forceinline__ void mma_tf32(float* c,
                                         unsigned a0, unsigned a1, unsigned a2, unsigned a3,
                                         unsigned b0, unsigned b1) {
    asm volatile(
        "mma.sync.aligned.m16n8k8.row.col.f32.tf32.tf32.f32 "
        "{%0,%1,%2,%3}, {%4,%5,%6,%7}, {%8,%9}, {%0,%1,%2,%3};\n"
        : "+f"(c[0]), "+f"(c[1]), "+f"(c[2]), "+f"(c[3])
        : "r"(a0), "r"(a1), "r"(a2), "r"(a3), "r"(b0), "r"(b1));
}

// Dekker split: x = hi(tf32-truncated) + lo. hi·hi + hi·lo + lo·hi ~ fp32 acc.
__device__ __forceinline__ void split2(float x, unsigned& hi, unsigned& lo) {
    unsigned xb = __float_as_uint(x);
    hi = xb & 0xffffe000u;
    lo = __float_as_uint(x - __uint_as_float(hi));
}

// ---------------------------------------------------------------------------
// Block-wide sum reduction (256 threads) for prep
// ---------------------------------------------------------------------------
__device__ __forceinline__ float blockReduceSum(float v, float* red) {
    #pragma unroll
    for (int o = 16; o > 0; o >>= 1) v += __shfl_xor_sync(0xffffffffu, v, o);
    int tid = threadIdx.x;
    if ((tid & 31) == 0) red[tid >> 5] = v;
    __syncthreads();
    if (tid < 32) {
        float x = (tid < 8) ? red[tid] : 0.f;
        #pragma unroll
        for (int o = 4; o > 0; o >>= 1) x += __shfl_xor_sync(0xffffffffu, x, o);
        if (tid == 0) red[0] = x;
    }
    __syncthreads();
    float r = red[0];
    __syncthreads();
    return r;
}

__device__ __forceinline__ void routing2(const float u0[2], const float u1[2],
                                         float vout[2], float* red) {
    float b0 = 0.f, b1 = 0.f;
    #pragma unroll
    for (int it = 0; it < 3; it++) {
        float mx = fmaxf(b0, b1);
        float e0 = __expf(b0 - mx), e1 = __expf(b1 - mx);
        float inv = 1.f / (e0 + e1);
        float c0 = e0 * inv, c1 = e1 * inv;
        float s0 = c0 * u0[0] + c1 * u1[0];
        float s1 = c0 * u0[1] + c1 * u1[1];
        float n2 = blockReduceSum(s0 * s0 + s1 * s1, red);
        float nrm = sqrtf(n2);
        float scl = n2 / ((1.f + n2) * (nrm + 1e-9f));
        vout[0] = scl * s0;
        vout[1] = scl * s1;
        if (it < 2) {
            b0 += blockReduceSum(u0[0] * vout[0] + u0[1] * vout[1], red);
            b1 += blockReduceSum(u1[0] * vout[0] + u1[1] * vout[1], red);
        }
    }
}

// ---------------------------------------------------------------------------
// Kernel 1: causal depthwise convs + capsule routing
// ---------------------------------------------------------------------------
__global__ void prep_kernel(const float* __restrict__ x,
                            const float* __restrict__ w3,
                            const float* __restrict__ w5) {
    __shared__ float red[8];
    int row = blockIdx.x;
    int n = row >> 11;
    int l = row & 2047;
    int tid = threadIdx.x;

    float xv[2], t3v[2], t5v[2];
    #pragma unroll
    for (int i = 0; i < 2; i++) {
        int c = tid + i * 256;
        const float* xb = x + (size_t)n * LQ * DD + c;
        float a3 = 0.f, a5 = 0.f, xx = 0.f;
        #pragma unroll
        for (int j = 0; j < 5; j++) {
            int ll = l - 4 + j;
            xx = (ll >= 0) ? xb[(size_t)ll * DD] : 0.f;
            a5 += w5[c * 5 + j] * xx;
            if (j >= 2) a3 += w3[c * 3 + (j - 2)] * xx;
        }
        xv[i] = xx; t3v[i] = a3; t5v[i] = a5;
    }

    float u0[2], u1[2], v[2];
    u0[0] = xv[0] - t3v[0]; u0[1] = xv[1] - t3v[1];
    u1[0] = xv[0] - t5v[0]; u1[1] = xv[1] - t5v[1];
    routing2(u0, u1, v, red);
    g_Xs[(size_t)row * DD + tid]       = v[0];
    g_Xs[(size_t)row * DD + tid + 256] = v[1];

    u0[0] = t3v[0]; u0[1] = t3v[1];
    u1[0] = t5v[0]; u1[1] = t5v[1];
    routing2(u0, u1, v, red);
    g_Xt[(size_t)row * DD + tid]       = v[0];
    g_Xt[(size_t)row * DD + tid + 256] = v[1];
}

// ---------------------------------------------------------------------------
// Kernel 2: flash attention, tf32 mma.sync 3-pass, 32x32 tiles
// grid = (L/32, N, 2), 256 threads
// ---------------------------------------------------------------------------
__global__ void __launch_bounds__(256, 1) attn_kernel() {
    extern __shared__ float sm[];
    float* Qs     = sm;                  // 32 x QP
    float* Ks     = Qs + 32 * QP;        // 32 x KP (keys == values)
    float* Ps     = Ks + 32 * KP;        // 32 x PP
    float* redm   = Ps + 32 * PP;        // 4 x 32
    float* redl   = redm + 128;          // 4 x 32
    float* m_s    = redl + 128;          // 32
    float* l_s    = m_s + 32;            // 32
    float* corr_s = l_s + 32;            // 32

    int zb = blockIdx.z;
    const float* X = zb ? g_Xt : g_Xs;
    int n = blockIdx.y;
    int qb = blockIdx.x;
    int tid = threadIdx.x;
    int w = tid >> 5, lane = tid & 31;
    int g4 = lane >> 2, tig = lane & 3;
    const float* Xn = X + (size_t)n * LQ * DD;
    int q0 = qb * 32;

    // load Q tile
    for (int i = tid; i < 32 * 128; i += 256) {
        int r = i >> 7, c4 = i & 127;
        *(float4*)&Qs[r * QP + c4 * 4] = ((const float4*)(Xn + (size_t)(q0 + r) * DD))[c4];
    }
    if (tid < 32) { m_s[tid] = -3.0e30f; l_s[tid] = 0.f; }

    // partitions: scores: warp = (rg rowgroup of 16) x (cg colgroup of 8)
    //             PV:     warp = (rg rowgroup of 16) x (cg2 colgroup of 128)
    int rg = w & 1, cg = w >> 1;

    float acc[16][4];
    #pragma unroll
    for (int i = 0; i < 16; i++) { acc[i][0] = acc[i][1] = acc[i][2] = acc[i][3] = 0.f; }

    int ar0 = (rg * 16 + g4) * QP;
    int ar1 = (rg * 16 + g4 + 8) * QP;
    int br  = (cg * 8 + g4) * KP;
    int par0 = (rg * 16 + g4) * PP;
    int par1 = (rg * 16 + g4 + 8) * PP;

    for (int kb = 0; kb <= qb; kb++) {
        __syncthreads();                        // S1: protect Ks/Ps/redl
        for (int i = tid; i < 32 * 128; i += 256) {
            int r = i >> 7, c4 = i & 127;
            *(float4*)&Ks[r * KP + c4 * 4] = ((const float4*)(Xn + (size_t)(kb * 32 + r) * DD))[c4];
        }
        __syncthreads();                        // S2: Ks ready

        // --- scores: S = Q K^T, 3-pass tf32 ---
        float sc[4] = {0.f, 0.f, 0.f, 0.f};
        #pragma unroll 8
        for (int ks = 0; ks < 64; ks++) {
            int k0 = ks * 8;
            unsigned h0, l0, h1, l1, h2, l2, h3, l3, hb0, lb0, hb1, lb1;
            split2(Qs[ar0 + k0 + tig],     h0, l0);
            split2(Qs[ar1 + k0 + tig],     h1, l1);
            split2(Qs[ar0 + k0 + tig + 4], h2, l2);
            split2(Qs[ar1 + k0 + tig + 4], h3, l3);
            split2(Ks[br + k0 + tig],      hb0, lb0);
            split2(Ks[br + k0 + tig + 4],  hb1, lb1);
            mma_tf32(sc, h0, h1, h2, h3, hb0, hb1);
            mma_tf32(sc, h0, h1, h2, h3, lb0, lb1);
            mma_tf32(sc, l0, l1, l2, l3, hb0, hb1);
        }
        // bias + causal mask
        int r0 = q0 + rg * 16 + g4, r1 = r0 + 8;
        int c0 = kb * 32 + cg * 8 + 2 * tig, c1 = c0 + 1;
        sc[0] = (r0 >= c0) ? sc[0] - DECAYF * (float)(r0 - c0) : -3.0e30f;
        sc[1] = (r0 >= c1) ? sc[1] - DECAYF * (float)(r0 - c1) : -3.0e30f;
        sc[2] = (r1 >= c0) ? sc[2] - DECAYF * (float)(r1 - c0) : -3.0e30f;
        sc[3] = (r1 >= c1) ? sc[3] - DECAYF * (float)(r1 - c1) : -3.0e30f;

        // warp-level row max over this warp's 8 cols
        float m0 = fmaxf(sc[0], sc[1]);
        float m1 = fmaxf(sc[2], sc[3]);
        m0 = fmaxf(m0, __shfl_xor_sync(0xffffffffu, m0, 1));
        m0 = fmaxf(m0, __shfl_xor_sync(0xffffffffu, m0, 2));
        m1 = fmaxf(m1, __shfl_xor_sync(0xffffffffu, m1, 1));
        m1 = fmaxf(m1, __shfl_xor_sync(0xffffffffu, m1, 2));
        if (tig == 0) {
            redm[cg * 32 + rg * 16 + g4]     = m0;
            redm[cg * 32 + rg * 16 + g4 + 8] = m1;
        }
        __syncthreads();                        // S3: redm ready
        if (w == 0) {
            int r = lane;
            float tm = fmaxf(fmaxf(redm[r], redm[32 + r]), fmaxf(redm[64 + r], redm[96 + r]));
            float mo = m_s[r];
            float mn = fmaxf(mo, tm);
            m_s[r] = mn;
            corr_s[r] = __expf(mo - mn);
        }
        __syncthreads();                        // S4: m_s/corr_s ready

        // P = exp(S - m), write to Ps + partial sums
        {
            float mn0 = m_s[rg * 16 + g4];
            float mn1 = m_s[rg * 16 + g4 + 8];
            float p0 = __expf(sc[0] - mn0);
            float p1 = __expf(sc[1] - mn0);
            float p2 = __expf(sc[2] - mn1);
            float p3 = __expf(sc[3] - mn1);
            *(float2*)&Ps[par0 + cg * 8 + 2 * tig] = make_float2(p0, p1);
            *(float2*)&Ps[par1 + cg * 8 + 2 * tig] = make_float2(p2, p3);
            float s0 = p0 + p1, s1 = p2 + p3;
            s0 += __shfl_xor_sync(0xffffffffu, s0, 1);
            s0 += __shfl_xor_sync(0xffffffffu, s0, 2);
            s1 += __shfl_xor_sync(0xffffffffu, s1, 1);
            s1 += __shfl_xor_sync(0xffffffffu, s1, 2);
            if (tig == 0) {
                redl[cg * 32 + rg * 16 + g4]     = s0;
                redl[cg * 32 + rg * 16 + g4 + 8] = s1;
            }
        }
        __syncthreads();                        // S5: Ps + redl ready
        if (w == 0) {
            int r = lane;
            l_s[r] = l_s[r] * corr_s[r] + redl[r] + redl[32 + r] + redl[64 + r] + redl[96 + r];
        }

        // --- PV: O += P V, 3-pass tf32 ---
        float cr0 = corr_s[rg * 16 + g4];
        float cr1 = corr_s[rg * 16 + g4 + 8];
        #pragma unroll
        for (int nf = 0; nf < 16; nf++) {
            acc[nf][0] *= cr0; acc[nf][1] *= cr0;
            acc[nf][2] *= cr1; acc[nf][3] *= cr1;
        }
        #pragma unroll
        for (int ks = 0; ks < 4; ks++) {
            int k0 = ks * 8;
            unsigned h0, l0, h1, l1, h2, l2, h3, l3;
            split2(Ps[par0 + k0 + tig],     h0, l0);
            split2(Ps[par1 + k0 + tig],     h1, l1);
            split2(Ps[par0 + k0 + tig + 4], h2, l2);
            split2(Ps[par1 + k0 + tig + 4], h3, l3);
            int vb0 = (k0 + tig) * KP;
            int vb1 = (k0 + tig + 4) * KP;
            #pragma unroll
            for (int nf = 0; nf < 16; nf++) {
                int n0 = cg * 128 + nf * 8 + g4;
                unsigned hv0, lv0, hv1, lv1;
                split2(Ks[vb0 + n0], hv0, lv0);
                split2(Ks[vb1 + n0], hv1, lv1);
                mma_tf32(acc[nf], h0, h1, h2, h3, hv0, hv1);
                mma_tf32(acc[nf], h0, h1, h2, h3, lv0, lv1);
                mma_tf32(acc[nf], l0, l1, l2, l3, hv0, hv1);
            }
        }
    }
    __syncthreads();

    float li0 = 1.f / l_s[rg * 16 + g4];
    float li1 = 1.f / l_s[rg * 16 + g4 + 8];
    int orow0 = n * LQ + q0 + rg * 16 + g4;
    int orow1 = orow0 + 8;
    #pragma unroll
    for (int nf = 0; nf < 16; nf++) {
        int col = zb * DD + cg * 128 + nf * 8 + 2 * tig;
        *(float2*)&g_cat[(size_t)orow0 * (2 * DD) + col] =
            make_float2(acc[nf][0] * li0, acc[nf][1] * li0);
        *(float2*)&g_cat[(size_t)orow1 * (2 * DD) + col] =
            make_float2(acc[nf][2] * li1, acc[nf][3] * li1);
    }
}

// ---------------------------------------------------------------------------
// Kernel 3: out[16384,512] = g_cat[16384,1024] @ W[512,1024]^T + bias
// tf32 mma.sync 3-pass, 64x64 tiles
// ---------------------------------------------------------------------------
__global__ void __launch_bounds__(256) fusion_kernel(const float* __restrict__ W,
                                                     const float* __restrict__ bias,
                                                     float* __restrict__ out) {
    __shared__ float As[64 * 36];
    __shared__ float Bs[64 * 36];
    int bm = blockIdx.x * 64;
    int bn = blockIdx.y * 64;
    int tid = threadIdx.x;
    int w = tid >> 5, lane = tid & 31;
    int g4 = lane >> 2, tig = lane & 3;
    int rg = w & 3, cg = w >> 2;

    float acc[4][4];
    #pragma unroll
    for (int i = 0; i < 4; i++) { acc[i][0] = acc[i][1] = acc[i][2] = acc[i][3] = 0.f; }

    int ar0 = (rg * 16 + g4) * 36;
    int ar1 = (rg * 16 + g4 + 8) * 36;

    for (int kc = 0; kc < 32; kc++) {
        __syncthreads();
        #pragma unroll
        for (int i = 0; i < 2; i++) {
            int idx = tid + i * 256;
            int r = idx >> 3, c = idx & 7;
            *(float4*)&As[r * 36 + c * 4] =
                *(const float4*)&g_cat[(size_t)(bm + r) * 1024 + kc * 32 + c * 4];
            *(float4*)&Bs[r * 36 + c * 4] =
                *(const float4*)&W[(size_t)(bn + r) * 1024 + kc * 32 + c * 4];
        }
        __syncthreads();
        #pragma unroll
        for (int ks = 0; ks < 4; ks++) {
            int k0 = ks * 8;
            unsigned h0, l0, h1, l1, h2, l2, h3, l3;
            split2(As[ar0 + k0 + tig],     h0, l0);
            split2(As[ar1 + k0 + tig],     h1, l1);
            split2(As[ar0 + k0 + tig + 4], h2, l2);
            split2(As[ar1 + k0 + tig + 4], h3, l3);
            #pragma unroll
            for (int nf = 0; nf < 4; nf++) {
                int brow = (cg * 32 + nf * 8 + g4) * 36;
                unsigned hb0, lb0, hb1, lb1;
                split2(Bs[brow + k0 + tig],     hb0, lb0);
                split2(Bs[brow + k0 + tig + 4], hb1, lb1);
                mma_tf32(acc[nf], h0, h1, h2, h3, hb0, hb1);
                mma_tf32(acc[nf], h0, h1, h2, h3, lb0, lb1);
                mma_tf32(acc[nf], l0, l1, l2, l3, hb0, hb1);
            }
        }
    }

    int orow0 = bm + rg * 16 + g4, orow1 = orow0 + 8;
    #pragma unroll
    for (int nf = 0; nf < 4; nf++) {
        int col = bn + cg * 32 + nf * 8 + 2 * tig;
        float b0v = bias[col], b1v = bias[col + 1];
        *(float2*)&out[(size_t)orow0 * 512 + col] = make_float2(acc[nf][0] + b0v, acc[nf][1] + b1v);
        *(float2*)&out[(size_t)orow1 * 512 + col] = make_float2(acc[nf][2] + b0v, acc[nf][3] + b1v);
    }
}

// ---------------------------------------------------------------------------
extern "C" void kernel_launch(void* const* d_in, const int* in_sizes, int n_in,
                              void* d_out, int out_size) {
    const float* x  = (const float*)d_in[0];
    const float* w3 = (const float*)d_in[1];
    const float* w5 = (const float*)d_in[2];
    const float* fw = (const float*)d_in[3];
    const float* fb = (const float*)d_in[4];
    float* out = (float*)d_out;

    prep_kernel<<<NB * LQ, 256>>>(x, w3, w5);

    size_t smem = (size_t)(32 * QP + 32 * KP + 32 * PP + 128 + 128 + 96) * sizeof(float);
    cudaFuncSetAttribute(attn_kernel,
                         cudaFuncAttributeMaxDynamicSharedMemorySize, (int)smem);
    dim3 ga(LQ / 32, NB, 2);
    attn_kernel<<<ga, 256, smem>>>();

    dim3 gf((NB * LQ) / 64, DD / 64);
    fusion_kernel<<<gf, 256>>>(fw, fb, out);
}

// round 5
// speedup vs baseline: 1.7825x; 1.0020x over previous
#include <cuda_runtime.h>
#include <math.h>

#define NB 8
#define LQ 2048
#define DD 512
#define DECAYF 0.2f
#define QP 516      // Q tile smem row stride (pad ≡ 4 mod 32 -> conflict-free A-frag LDS)
#define KP 516      // K/V tile smem row stride
#define PP 36       // P tile smem row stride

// Scratch (device globals: allocation-free per harness rules)
__device__ float g_Xs[NB * LQ * DD];
__device__ float g_Xt[NB * LQ * DD];
__device__ float g_cat[NB * LQ * 2 * DD];

// ---------------------------------------------------------------------------
// tf32 mma.sync helper: D += A(16x8) * B(8x8), accumulate in place
// ---------------------------------------------------------------------------
__device__ __forceinline__ void mma_tf32(float* c,
                                         unsigned a0, unsigned a1, unsigned a2, unsigned a3,
                                         unsigned b0, unsigned b1) {
    asm volatile(
        "mma.sync.aligned.m16n8k8.row.col.f32.tf32.tf32.f32 "
        "{%0,%1,%2,%3}, {%4,%5,%6,%7}, {%8,%9}, {%0,%1,%2,%3};\n"
        : "+f"(c[0]), "+f"(c[1]), "+f"(c[2]), "+f"(c[3])
        : "r"(a0), "r"(a1), "r"(a2), "r"(a3), "r"(b0), "r"(b1));
}

// Dekker split: x = hi(tf32-truncated) + lo. hi·hi + hi·lo + lo·hi ~ fp32 acc.
__device__ __forceinline__ void split2(float x, unsigned& hi, unsigned& lo) {
    unsigned xb = __float_as_uint(x);
    hi = xb & 0xffffe000u;
    lo = __float_as_uint(x - __uint_as_float(hi));
}

// ---------------------------------------------------------------------------
// Block-wide sum reduction (256 threads) for prep
// ---------------------------------------------------------------------------
__device__ __forceinline__ float blockReduceSum(float v, float* red) {
    #pragma unroll
    for (int o = 16; o > 0; o >>= 1) v += __shfl_xor_sync(0xffffffffu, v, o);
    int tid = threadIdx.x;
    if ((tid & 31) == 0) red[tid >> 5] = v;
    __syncthreads();
    if (tid < 32) {
        float x = (tid < 8) ? red[tid] : 0.f;
        #pragma unroll
        for (int o = 4; o > 0; o >>= 1) x += __shfl_xor_sync(0xffffffffu, x, o);
        if (tid == 0) red[0] = x;
    }
    __syncthreads();
    float r = red[0];
    __syncthreads();
    return r;
}

__device__ __forceinline__ void routing2(const float u0[2], const float u1[2],
                                         float vout[2], float* red) {
    float b0 = 0.f, b1 = 0.f;
    #pragma unroll
    for (int it = 0; it < 3; it++) {
        float mx = fmaxf(b0, b1);
        float e0 = __expf(b0 - mx), e1 = __expf(b1 - mx);
        float inv = 1.f / (e0 + e1);
        float c0 = e0 * inv, c1 = e1 * inv;
        float s0 = c0 * u0[0] + c1 * u1[0];
        float s1 = c0 * u0[1] + c1 * u1[1];
        float n2 = blockReduceSum(s0 * s0 + s1 * s1, red);
        float nrm = sqrtf(n2);
        float scl = n2 / ((1.f + n2) * (nrm + 1e-9f));
        vout[0] = scl * s0;
        vout[1] = scl * s1;
        if (it < 2) {
            b0 += blockReduceSum(u0[0] * vout[0] + u0[1] * vout[1], red);
            b1 += blockReduceSum(u1[0] * vout[0] + u1[1] * vout[1], red);
        }
    }
}

// ---------------------------------------------------------------------------
// Kernel 1: causal depthwise convs + capsule routing
// ---------------------------------------------------------------------------
__global__ void prep_kernel(const float* __restrict__ x,
                            const float* __restrict__ w3,
                            const float* __restrict__ w5) {
    __shared__ float red[8];
    int row = blockIdx.x;
    int n = row >> 11;
    int l = row & 2047;
    int tid = threadIdx.x;

    float xv[2], t3v[2], t5v[2];
    #pragma unroll
    for (int i = 0; i < 2; i++) {
        int c = tid + i * 256;
        const float* xb = x + (size_t)n * LQ * DD + c;
        float a3 = 0.f, a5 = 0.f, xx = 0.f;
        #pragma unroll
        for (int j = 0; j < 5; j++) {
            int ll = l - 4 + j;
            xx = (ll >= 0) ? xb[(size_t)ll * DD] : 0.f;
            a5 += w5[c * 5 + j] * xx;
            if (j >= 2) a3 += w3[c * 3 + (j - 2)] * xx;
        }
        xv[i] = xx; t3v[i] = a3; t5v[i] = a5;
    }

    float u0[2], u1[2], v[2];
    u0[0] = xv[0] - t3v[0]; u0[1] = xv[1] - t3v[1];
    u1[0] = xv[0] - t5v[0]; u1[1] = xv[1] - t5v[1];
    routing2(u0, u1, v, red);
    g_Xs[(size_t)row * DD + tid]       = v[0];
    g_Xs[(size_t)row * DD + tid + 256] = v[1];

    u0[0] = t3v[0]; u0[1] = t3v[1];
    u1[0] = t5v[0]; u1[1] = t5v[1];
    routing2(u0, u1, v, red);
    g_Xt[(size_t)row * DD + tid]       = v[0];
    g_Xt[(size_t)row * DD + tid + 256] = v[1];
}

// ---------------------------------------------------------------------------
// Kernel 2: flash attention, tf32 mma.sync 3-pass, 32x32 tiles
// grid = (L/32, N, 2), 256 threads
// ---------------------------------------------------------------------------
__global__ void __launch_bounds__(256, 1) attn_kernel() {
    extern __shared__ float sm[];
    float* Qs     = sm;                  // 32 x QP
    float* Ks     = Qs + 32 * QP;        // 32 x KP (keys == values)
    float* Ps     = Ks + 32 * KP;        // 32 x PP
    float* redm   = Ps + 32 * PP;        // 4 x 32
    float* redl   = redm + 128;          // 4 x 32
    float* m_s    = redl + 128;          // 32
    float* l_s    = m_s + 32;            // 32
    float* corr_s = l_s + 32;            // 32

    int zb = blockIdx.z;
    const float* X = zb ? g_Xt : g_Xs;
    int n = blockIdx.y;
    int qb = blockIdx.x;
    int tid = threadIdx.x;
    int w = tid >> 5, lane = tid & 31;
    int g4 = lane >> 2, tig = lane & 3;
    const float* Xn = X + (size_t)n * LQ * DD;
    int q0 = qb * 32;

    // load Q tile
    for (int i = tid; i < 32 * 128; i += 256) {
        int r = i >> 7, c4 = i & 127;
        *(float4*)&Qs[r * QP + c4 * 4] = ((const float4*)(Xn + (size_t)(q0 + r) * DD))[c4];
    }
    if (tid < 32) { m_s[tid] = -3.0e30f; l_s[tid] = 0.f; }

    // partitions: scores: warp = (rg rowgroup of 16) x (cg colgroup of 8)
    //             PV:     warp = (rg rowgroup of 16) x (cg2 colgroup of 128)
    int rg = w & 1, cg = w >> 1;

    float acc[16][4];
    #pragma unroll
    for (int i = 0; i < 16; i++) { acc[i][0] = acc[i][1] = acc[i][2] = acc[i][3] = 0.f; }

    int ar0 = (rg * 16 + g4) * QP;
    int ar1 = (rg * 16 + g4 + 8) * QP;
    int br  = (cg * 8 + g4) * KP;
    int par0 = (rg * 16 + g4) * PP;
    int par1 = (rg * 16 + g4 + 8) * PP;

    for (int kb = 0; kb <= qb; kb++) {
        __syncthreads();                        // S1: protect Ks/Ps/redl
        for (int i = tid; i < 32 * 128; i += 256) {
            int r = i >> 7, c4 = i & 127;
            *(float4*)&Ks[r * KP + c4 * 4] = ((const float4*)(Xn + (size_t)(kb * 32 + r) * DD))[c4];
        }
        __syncthreads();                        // S2: Ks ready

        // --- scores: S = Q K^T, 3-pass tf32 ---
        float sc[4] = {0.f, 0.f, 0.f, 0.f};
        #pragma unroll 8
        for (int ks = 0; ks < 64; ks++) {
            int k0 = ks * 8;
            unsigned h0, l0, h1, l1, h2, l2, h3, l3, hb0, lb0, hb1, lb1;
            split2(Qs[ar0 + k0 + tig],     h0, l0);
            split2(Qs[ar1 + k0 + tig],     h1, l1);
            split2(Qs[ar0 + k0 + tig + 4], h2, l2);
            split2(Qs[ar1 + k0 + tig + 4], h3, l3);
            split2(Ks[br + k0 + tig],      hb0, lb0);
            split2(Ks[br + k0 + tig + 4],  hb1, lb1);
            mma_tf32(sc, h0, h1, h2, h3, hb0, hb1);
            mma_tf32(sc, h0, h1, h2, h3, lb0, lb1);
            mma_tf32(sc, l0, l1, l2, l3, hb0, hb1);
        }
        // bias + causal mask
        int r0 = q0 + rg * 16 + g4, r1 = r0 + 8;
        int c0 = kb * 32 + cg * 8 + 2 * tig, c1 = c0 + 1;
        sc[0] = (r0 >= c0) ? sc[0] - DECAYF * (float)(r0 - c0) : -3.0e30f;
        sc[1] = (r0 >= c1) ? sc[1] - DECAYF * (float)(r0 - c1) : -3.0e30f;
        sc[2] = (r1 >= c0) ? sc[2] - DECAYF * (float)(r1 - c0) : -3.0e30f;
        sc[3] = (r1 >= c1) ? sc[3] - DECAYF * (float)(r1 - c1) : -3.0e30f;

        // warp-level row max over this warp's 8 cols
        float m0 = fmaxf(sc[0], sc[1]);
        float m1 = fmaxf(sc[2], sc[3]);
        m0 = fmaxf(m0, __shfl_xor_sync(0xffffffffu, m0, 1));
        m0 = fmaxf(m0, __shfl_xor_sync(0xffffffffu, m0, 2));
        m1 = fmaxf(m1, __shfl_xor_sync(0xffffffffu, m1, 1));
        m1 = fmaxf(m1, __shfl_xor_sync(0xffffffffu, m1, 2));
        if (tig == 0) {
            redm[cg * 32 + rg * 16 + g4]     = m0;
            redm[cg * 32 + rg * 16 + g4 + 8] = m1;
        }
        __syncthreads();                        // S3: redm ready
        if (w == 0) {
            int r = lane;
            float tm = fmaxf(fmaxf(redm[r], redm[32 + r]), fmaxf(redm[64 + r], redm[96 + r]));
            float mo = m_s[r];
            float mn = fmaxf(mo, tm);
            m_s[r] = mn;
            corr_s[r] = __expf(mo - mn);
        }
        __syncthreads();                        // S4: m_s/corr_s ready

        // P = exp(S - m), write to Ps + partial sums
        {
            float mn0 = m_s[rg * 16 + g4];
            float mn1 = m_s[rg * 16 + g4 + 8];
            float p0 = __expf(sc[0] - mn0);
            float p1 = __expf(sc[1] - mn0);
            float p2 = __expf(sc[2] - mn1);
            float p3 = __expf(sc[3] - mn1);
            *(float2*)&Ps[par0 + cg * 8 + 2 * tig] = make_float2(p0, p1);
            *(float2*)&Ps[par1 + cg * 8 + 2 * tig] = make_float2(p2, p3);
            float s0 = p0 + p1, s1 = p2 + p3;
            s0 += __shfl_xor_sync(0xffffffffu, s0, 1);
            s0 += __shfl_xor_sync(0xffffffffu, s0, 2);
            s1 += __shfl_xor_sync(0xffffffffu, s1, 1);
            s1 += __shfl_xor_sync(0xffffffffu, s1, 2);
            if (tig == 0) {
                redl[cg * 32 + rg * 16 + g4]     = s0;
                redl[cg * 32 + rg * 16 + g4 + 8] = s1;
            }
        }
        __syncthreads();                        // S5: Ps + redl ready
        if (w == 0) {
            int r = lane;
            l_s[r] = l_s[r] * corr_s[r] + redl[r] + redl[32 + r] + redl[64 + r] + redl[96 + r];
        }

        // --- PV: O += P V, 3-pass tf32 ---
        float cr0 = corr_s[rg * 16 + g4];
        float cr1 = corr_s[rg * 16 + g4 + 8];
        #pragma unroll
        for (int nf = 0; nf < 16; nf++) {
            acc[nf][0] *= cr0; acc[nf][1] *= cr0;
            acc[nf][2] *= cr1; acc[nf][3] *= cr1;
        }
        #pragma unroll
        for (int ks = 0; ks < 4; ks++) {
            int k0 = ks * 8;
            unsigned h0, l0, h1, l1, h2, l2, h3, l3;
            split2(Ps[par0 + k0 + tig],     h0, l0);
            split2(Ps[par1 + k0 + tig],     h1, l1);
            split2(Ps[par0 + k0 + tig + 4], h2, l2);
            split2(Ps[par1 + k0 + tig + 4], h3, l3);
            int vb0 = (k0 + tig) * KP;
            int vb1 = (k0 + tig + 4) * KP;
            #pragma unroll
            for (int nf = 0; nf < 16; nf++) {
                int n0 = cg * 128 + nf * 8 + g4;
                unsigned hv0, lv0, hv1, lv1;
                split2(Ks[vb0 + n0], hv0, lv0);
                split2(Ks[vb1 + n0], hv1, lv1);
                mma_tf32(acc[nf], h0, h1, h2, h3, hv0, hv1);
                mma_tf32(acc[nf], h0, h1, h2, h3, lv0, lv1);
                mma_tf32(acc[nf], l0, l1, l2, l3, hv0, hv1);
            }
        }
    }
    __syncthreads();

    float li0 = 1.f / l_s[rg * 16 + g4];
    float li1 = 1.f / l_s[rg * 16 + g4 + 8];
    int orow0 = n * LQ + q0 + rg * 16 + g4;
    int orow1 = orow0 + 8;
    #pragma unroll
    for (int nf = 0; nf < 16; nf++) {
        int col = zb * DD + cg * 128 + nf * 8 + 2 * tig;
        *(float2*)&g_cat[(size_t)orow0 * (2 * DD) + col] =
            make_float2(acc[nf][0] * li0, acc[nf][1] * li0);
        *(float2*)&g_cat[(size_t)orow1 * (2 * DD) + col] =
            make_float2(acc[nf][2] * li1, acc[nf][3] * li1);
    }
}

// ---------------------------------------------------------------------------
// Kernel 3: out[16384,512] = g_cat[16384,1024] @ W[512,1024]^T + bias
// tf32 mma.sync 3-pass, 64x64 tiles
// ---------------------------------------------------------------------------
__global__ void __launch_bounds__(256) fusion_kernel(const float* __restrict__ W,
                                                     const float* __restrict__ bias,
                                                     float* __restrict__ out) {
    __shared__ float As[64 * 36];
    __shared__ float Bs[64 * 36];
    int bm = blockIdx.x * 64;
    int bn = blockIdx.y * 64;
    int tid = threadIdx.x;
    int w = tid >> 5, lane = tid & 31;
    int g4 = lane >> 2, tig = lane & 3;
    int rg = w & 3, cg = w >> 2;

    float acc[4][4];
    #pragma unroll
    for (int i = 0; i < 4; i++) { acc[i][0] = acc[i][1] = acc[i][2] = acc[i][3] = 0.f; }

    int ar0 = (rg * 16 + g4) * 36;
    int ar1 = (rg * 16 + g4 + 8) * 36;

    for (int kc = 0; kc < 32; kc++) {
        __syncthreads();
        #pragma unroll
        for (int i = 0; i < 2; i++) {
            int idx = tid + i * 256;
            int r = idx >> 3, c = idx & 7;
            *(float4*)&As[r * 36 + c * 4] =
                *(const float4*)&g_cat[(size_t)(bm + r) * 1024 + kc * 32 + c * 4];
            *(float4*)&Bs[r * 36 + c * 4] =
                *(const float4*)&W[(size_t)(bn + r) * 1024 + kc * 32 + c * 4];
        }
        __syncthreads();
        #pragma unroll
        for (int ks = 0; ks < 4; ks++) {
            int k0 = ks * 8;
            unsigned h0, l0, h1, l1, h2, l2, h3, l3;
            split2(As[ar0 + k0 + tig],     h0, l0);
            split2(As[ar1 + k0 + tig],     h1, l1);
            split2(As[ar0 + k0 + tig + 4], h2, l2);
            split2(As[ar1 + k0 + tig + 4], h3, l3);
            #pragma unroll
            for (int nf = 0; nf < 4; nf++) {
                int brow = (cg * 32 + nf * 8 + g4) * 36;
                unsigned hb0, lb0, hb1, lb1;
                split2(Bs[brow + k0 + tig],     hb0, lb0);
                split2(Bs[brow + k0 + tig + 4], hb1, lb1);
                mma_tf32(acc[nf], h0, h1, h2, h3, hb0, hb1);
                mma_tf32(acc[nf], h0, h1, h2, h3, lb0, lb1);
                mma_tf32(acc[nf], l0, l1, l2, l3, hb0, hb1);
            }
        }
    }

    int orow0 = bm + rg * 16 + g4, orow1 = orow0 + 8;
    #pragma unroll
    for (int nf = 0; nf < 4; nf++) {
        int col = bn + cg * 32 + nf * 8 + 2 * tig;
        float b0v = bias[col], b1v = bias[col + 1];
        *(float2*)&out[(size_t)orow0 * 512 + col] = make_float2(acc[nf][0] + b0v, acc[nf][1] + b1v);
        *(float2*)&out[(size_t)orow1 * 512 + col] = make_float2(acc[nf][2] + b0v, acc[nf][3] + b1v);
    }
}

// ---------------------------------------------------------------------------
extern "C" void kernel_launch(void* const* d_in, const int* in_sizes, int n_in,
                              void* d_out, int out_size) {
    const float* x  = (const float*)d_in[0];
    const float* w3 = (const float*)d_in[1];
    const float* w5 = (const float*)d_in[2];
    const float* fw = (const float*)d_in[3];
    const float* fb = (const float*)d_in[4];
    float* out = (float*)d_out;

    prep_kernel<<<NB * LQ, 256>>>(x, w3, w5);

    size_t smem = (size_t)(32 * QP + 32 * KP + 32 * PP + 128 + 128 + 96) * sizeof(float);
    cudaFuncSetAttribute(attn_kernel,
                         cudaFuncAttributeMaxDynamicSharedMemorySize, (int)smem);
    dim3 ga(LQ / 32, NB, 2);
    attn_kernel<<<ga, 256, smem>>>();

    dim3 gf((NB * LQ) / 64, DD / 64);
    fusion_kernel<<<gf, 256>>>(fw, fb, out);
}